// round 6
// baseline (speedup 1.0000x reference)
#include <cuda_runtime.h>
#include <cuda_bf16.h>
#include <math.h>

#define B_ 2
#define S_ 2048
#define D_ 2048
#define H_ 32
#define G_ 8
#define HD_ 64
#define GS_ (H_/G_)
#define M_ (B_*S_)

typedef unsigned int uint32;

// ---- tensor-core helpers ----
__device__ __forceinline__ void ldsm4(uint32 &r0, uint32 &r1, uint32 &r2, uint32 &r3,
                                      const void* p) {
    uint32 a = (uint32)__cvta_generic_to_shared(p);
    asm volatile("ldmatrix.sync.aligned.m8n8.x4.shared.b16 {%0,%1,%2,%3},[%4];"
                 : "=r"(r0), "=r"(r1), "=r"(r2), "=r"(r3) : "r"(a));
}
__device__ __forceinline__ void ldsm2t(uint32 &r0, uint32 &r1, const void* p) {
    uint32 a = (uint32)__cvta_generic_to_shared(p);
    asm volatile("ldmatrix.sync.aligned.m8n8.x2.trans.shared.b16 {%0,%1},[%2];"
                 : "=r"(r0), "=r"(r1) : "r"(a));
}
__device__ __forceinline__ void mma16816(float c[4], const uint32 a[4],
                                         uint32 b0, uint32 b1) {
    asm volatile(
        "mma.sync.aligned.m16n8k16.row.col.f32.bf16.bf16.f32 "
        "{%0,%1,%2,%3},{%4,%5,%6,%7},{%8,%9},{%0,%1,%2,%3};"
        : "+f"(c[0]), "+f"(c[1]), "+f"(c[2]), "+f"(c[3])
        : "r"(a[0]), "r"(a[1]), "r"(a[2]), "r"(a[3]), "r"(b0), "r"(b1));
}
// split two fp32 into packed bf16 hi + packed bf16 lo (p0 in low half)
__device__ __forceinline__ void split2(float p0, float p1, uint32 &h, uint32 &l) {
    asm("cvt.rn.bf16x2.f32 %0, %1, %2;" : "=r"(h) : "f"(p1), "f"(p0));
    float r0 = __uint_as_float(h << 16);
    float r1 = __uint_as_float(h & 0xffff0000u);
    asm("cvt.rn.bf16x2.f32 %0, %1, %2;" : "=r"(l) : "f"(p1 - r1), "f"(p0 - r0));
}
__device__ __forceinline__ void cvt4(float4 v, uint2 &hi, uint2 &lo) {
    split2(v.x, v.y, hi.x, lo.x);
    split2(v.z, v.w, hi.y, lo.y);
}
// ---- cp.async ----
__device__ __forceinline__ void cpa16(void* dst, const void* src) {
    uint32 d = (uint32)__cvta_generic_to_shared(dst);
    asm volatile("cp.async.ca.shared.global [%0],[%1],16;" :: "r"(d), "l"(src));
}
#define CP_COMMIT() asm volatile("cp.async.commit_group;")
#define CP_WAIT0()  asm volatile("cp.async.wait_group 0;")

// ---- Scratch device globals ----
__device__ float g_qf[(size_t)M_*H_*HD_];
__device__ float g_kf[(size_t)M_*G_*HD_];
__device__ float g_vf[(size_t)M_*G_*HD_];
__device__ __nv_bfloat16 g_xh[(size_t)M_*D_],     g_xl[(size_t)M_*D_];
__device__ __nv_bfloat16 g_wqh[(size_t)H_*HD_*D_], g_wql[(size_t)H_*HD_*D_];
__device__ __nv_bfloat16 g_wkh[(size_t)G_*HD_*D_], g_wkl[(size_t)G_*HD_*D_];
__device__ __nv_bfloat16 g_wvh[(size_t)G_*HD_*D_], g_wvl[(size_t)G_*HD_*D_];
__device__ __nv_bfloat16 g_woh[(size_t)D_*H_*HD_], g_wol[(size_t)D_*H_*HD_];
__device__ __nv_bfloat16 g_qh[(size_t)M_*H_*HD_],  g_ql[(size_t)M_*H_*HD_];
__device__ __nv_bfloat16 g_kh[(size_t)M_*G_*HD_],  g_kl[(size_t)M_*G_*HD_];
__device__ __nv_bfloat16 g_vh[(size_t)M_*G_*HD_],  g_vl[(size_t)M_*G_*HD_];
__device__ __nv_bfloat16 g_ch[(size_t)M_*H_*HD_],  g_cl[(size_t)M_*H_*HD_];

// ---------------------------------------------------------------------------
// fp32 -> bf16 hi/lo split (vectorized)
// ---------------------------------------------------------------------------
__global__ __launch_bounds__(256) void split_f32(
    const float* __restrict__ s, __nv_bfloat16* __restrict__ h,
    __nv_bfloat16* __restrict__ l, int n4)
{
    int i = blockIdx.x * blockDim.x + threadIdx.x;
    if (i < n4) {
        float4 v = ((const float4*)s)[i];
        uint2 hi, lo; cvt4(v, hi, lo);
        ((uint2*)h)[i] = hi;
        ((uint2*)l)[i] = lo;
    }
}

// ---------------------------------------------------------------------------
// NT GEMM body: bf16 hi/lo inputs, fp32 out. CTA 128x64x32, 256 thr (validated).
// ---------------------------------------------------------------------------
#define BM 128
#define BN 64
#define BKK 32
#define ASTR 40

__device__ __forceinline__ void gemm_body(
    const __nv_bfloat16* __restrict__ Ahg, const __nv_bfloat16* __restrict__ Alg,
    const __nv_bfloat16* __restrict__ Bhg, const __nv_bfloat16* __restrict__ Blg,
    float* __restrict__ C, int N, int K, int m0, int n0,
    __nv_bfloat16* Ah, __nv_bfloat16* Al, __nv_bfloat16* Bh, __nv_bfloat16* Bl)
{
    const int tid  = threadIdx.x;
    const int lane = tid & 31;
    const int warp = tid >> 5;
    const int wm = (warp >> 1) * 32;
    const int wn = (warp & 1) * 32;

    const int a_lr = lane & 15;
    const int a_k8 = ((lane >> 4) & 1) << 3;
    const int b_nr = (((lane >> 4) & 1) << 3) | (lane & 7);
    const int b_k8 = ((lane >> 3) & 1) << 3;

    float acc[2][4][4];
    #pragma unroll
    for (int i = 0; i < 2; i++)
        #pragma unroll
        for (int j = 0; j < 4; j++)
            #pragma unroll
            for (int t = 0; t < 4; t++) acc[i][j][t] = 0.f;

    // staged-register prefetch: A tile 128 rows x 4 chunks (2 per thread),
    // B tile 64 rows x 4 chunks (1 per thread); chunk = 8 bf16 = 16B.
    const int a_row = tid >> 2, a_c8 = (tid & 3) << 3;
    const int b_row = tid >> 2, b_c8 = (tid & 3) << 3;

    uint4 arh[2], arl[2], brh, brl;
    #pragma unroll
    for (int it = 0; it < 2; it++) {
        int row = a_row + it * 64;
        arh[it] = *(const uint4*)(Ahg + (size_t)(m0 + row) * K + a_c8);
        arl[it] = *(const uint4*)(Alg + (size_t)(m0 + row) * K + a_c8);
    }
    brh = *(const uint4*)(Bhg + (size_t)(n0 + b_row) * K + b_c8);
    brl = *(const uint4*)(Blg + (size_t)(n0 + b_row) * K + b_c8);

    for (int kb = 0; kb < K; kb += BKK) {
        #pragma unroll
        for (int it = 0; it < 2; it++) {
            int row = a_row + it * 64;
            *(uint4*)&Ah[row * ASTR + a_c8] = arh[it];
            *(uint4*)&Al[row * ASTR + a_c8] = arl[it];
        }
        *(uint4*)&Bh[b_row * ASTR + b_c8] = brh;
        *(uint4*)&Bl[b_row * ASTR + b_c8] = brl;
        __syncthreads();

        if (kb + BKK < K) {
            #pragma unroll
            for (int it = 0; it < 2; it++) {
                int row = a_row + it * 64;
                arh[it] = *(const uint4*)(Ahg + (size_t)(m0 + row) * K + kb + BKK + a_c8);
                arl[it] = *(const uint4*)(Alg + (size_t)(m0 + row) * K + kb + BKK + a_c8);
            }
            brh = *(const uint4*)(Bhg + (size_t)(n0 + b_row) * K + kb + BKK + b_c8);
            brl = *(const uint4*)(Blg + (size_t)(n0 + b_row) * K + kb + BKK + b_c8);
        }

        #pragma unroll
        for (int ks = 0; ks < BKK; ks += 16) {
            uint32 ah[2][4], al[2][4], bh[2][4], bl[2][4];
            #pragma unroll
            for (int mi = 0; mi < 2; mi++) {
                int off = (wm + mi * 16 + a_lr) * ASTR + ks + a_k8;
                ldsm4(ah[mi][0], ah[mi][1], ah[mi][2], ah[mi][3], &Ah[off]);
                ldsm4(al[mi][0], al[mi][1], al[mi][2], al[mi][3], &Al[off]);
            }
            #pragma unroll
            for (int p = 0; p < 2; p++) {
                int off = (wn + p * 16 + b_nr) * ASTR + ks + b_k8;
                ldsm4(bh[p][0], bh[p][1], bh[p][2], bh[p][3], &Bh[off]);
                ldsm4(bl[p][0], bl[p][1], bl[p][2], bl[p][3], &Bl[off]);
            }
            #pragma unroll
            for (int mi = 0; mi < 2; mi++)
                #pragma unroll
                for (int ni = 0; ni < 4; ni++) {
                    int p = ni >> 1, s = (ni & 1) * 2;
                    mma16816(acc[mi][ni], ah[mi], bh[p][s], bh[p][s+1]);
                    mma16816(acc[mi][ni], ah[mi], bl[p][s], bl[p][s+1]);
                    mma16816(acc[mi][ni], al[mi], bh[p][s], bh[p][s+1]);
                }
        }
        __syncthreads();
    }

    const int gq = lane >> 2, t = lane & 3;
    #pragma unroll
    for (int mi = 0; mi < 2; mi++)
        #pragma unroll
        for (int ni = 0; ni < 4; ni++) {
            int row = m0 + wm + mi * 16 + gq;
            int col = n0 + wn + ni * 8 + t * 2;
            *(float2*)(C + (size_t)row * N + col)       = make_float2(acc[mi][ni][0], acc[mi][ni][1]);
            *(float2*)(C + (size_t)(row + 8) * N + col) = make_float2(acc[mi][ni][2], acc[mi][ni][3]);
        }
}

// merged QKV projection: 48 n-blocks = 32 (Wq) + 8 (Wk) + 8 (Wv)
__global__ __launch_bounds__(256) void gemm_qkv()
{
    __shared__ __align__(16) __nv_bfloat16 Ah[BM*ASTR], Al[BM*ASTR];
    __shared__ __align__(16) __nv_bfloat16 Bh[BN*ASTR], Bl[BN*ASTR];

    int nb = blockIdx.x;
    const __nv_bfloat16 *Bhg, *Blg; float* C; int N, n0;
    if (nb < 32)      { Bhg = g_wqh; Blg = g_wql; C = g_qf; N = H_*HD_; n0 = nb * 64; }
    else if (nb < 40) { Bhg = g_wkh; Blg = g_wkl; C = g_kf; N = G_*HD_; n0 = (nb - 32) * 64; }
    else              { Bhg = g_wvh; Blg = g_wvl; C = g_vf; N = G_*HD_; n0 = (nb - 40) * 64; }

    gemm_body(g_xh, g_xl, Bhg, Blg, C, N, D_, blockIdx.y * BM, n0, Ah, Al, Bh, Bl);
}

// output projection: A = ctx (bf16 hi/lo), B = Wo, C = out fp32
__global__ __launch_bounds__(256) void gemm_o(float* __restrict__ out)
{
    __shared__ __align__(16) __nv_bfloat16 Ah[BM*ASTR], Al[BM*ASTR];
    __shared__ __align__(16) __nv_bfloat16 Bh[BN*ASTR], Bl[BN*ASTR];
    gemm_body(g_ch, g_cl, g_woh, g_wol, out, D_, H_*HD_,
              blockIdx.y * BM, blockIdx.x * 64, Ah, Al, Bh, Bl);
}

// ---------------------------------------------------------------------------
// Fused RMSNorm + RoPE + scale, emitting bf16 hi/lo directly.
// ---------------------------------------------------------------------------
__global__ __launch_bounds__(256) void rms_rope_split(
    const float* __restrict__ t, __nv_bfloat16* __restrict__ th,
    __nv_bfloat16* __restrict__ tl, const float* __restrict__ cosp,
    const float* __restrict__ sinp, const float* __restrict__ scale,
    int NH, float mul)
{
    const int warp = (blockIdx.x * blockDim.x + threadIdx.x) >> 5;
    const int lane = threadIdx.x & 31;
    const int s = (warp / NH) % S_;
    const float* p = t + (size_t)warp * HD_;

    float t1 = p[lane];
    float t2 = p[lane + 32];
    float ss = t1 * t1 + t2 * t2;
    #pragma unroll
    for (int o = 16; o > 0; o >>= 1) ss += __shfl_xor_sync(0xffffffffu, ss, o);
    float rs = rsqrtf(ss * (1.0f / HD_) + 1e-6f);

    float n1 = t1 * rs * (1.0f + scale[lane]);
    float n2 = t2 * rs * (1.0f + scale[lane + 32]);

    float c1 = cosp[s * HD_ + lane],      c2 = cosp[s * HD_ + lane + 32];
    float s1 = sinp[s * HD_ + lane],      s2 = sinp[s * HD_ + lane + 32];
    float o1 = (n1 * c1 - n2 * s1) * mul;
    float o2 = (n2 * c2 + n1 * s2) * mul;

    __nv_bfloat16 h1 = __float2bfloat16(o1);
    __nv_bfloat16 h2 = __float2bfloat16(o2);
    size_t base = (size_t)warp * HD_;
    th[base + lane]      = h1;
    th[base + lane + 32] = h2;
    tl[base + lane]      = __float2bfloat16(o1 - __bfloat162float(h1));
    tl[base + lane + 32] = __float2bfloat16(o2 - __bfloat162float(h2));
}

// ---------------------------------------------------------------------------
// Tensor-core causal flash attention, pre-split bf16 inputs, cp.async tiles.
// Block = (b, h, 64 q-rows). 4 warps x 16 rows. Key tiles of 64.
// Tiles are 64 rows x 64 bf16 = 64 rows x 8 chunks of 16B.
// ---------------------------------------------------------------------------
#define TSTR 72
#define NEG_BIG (-1e30f)

__global__ __launch_bounds__(128) void attn_tc(
    const __nv_bfloat16* __restrict__ qh, const __nv_bfloat16* __restrict__ qlp,
    const __nv_bfloat16* __restrict__ kh, const __nv_bfloat16* __restrict__ kl,
    const __nv_bfloat16* __restrict__ vh, const __nv_bfloat16* __restrict__ vl,
    __nv_bfloat16* __restrict__ ch, __nv_bfloat16* __restrict__ cl)
{
    __shared__ __align__(16) __nv_bfloat16 Kh[64*TSTR];
    __shared__ __align__(16) __nv_bfloat16 Kl[64*TSTR];
    __shared__ __align__(16) __nv_bfloat16 Vh[64*TSTR];
    __shared__ __align__(16) __nv_bfloat16 Vl[64*TSTR];

    const int tid  = threadIdx.x;
    const int lane = tid & 31;
    const int warp = tid >> 5;
    const int qt = blockIdx.x, h = blockIdx.y, b = blockIdx.z;
    const int g  = h / GS_;
    const int q0 = qt * 64;

    const int a_lr = lane & 15;
    const int a_k8 = ((lane >> 4) & 1) << 3;
    const int b_nr = (((lane >> 4) & 1) << 3) | (lane & 7);
    const int b_k8 = ((lane >> 3) & 1) << 3;
    const int v_r  = lane & 15;

    // ---- Q tile via cp.async into Kh/Kl, then fragments to registers ----
    // 512 chunks: row = f>>3 (0..63), c8 = (f&7)*8 (0..56)
    #pragma unroll
    for (int it = 0; it < 4; it++) {
        int f = it * 128 + tid;
        int row = f >> 3, c8 = (f & 7) << 3;
        size_t src = ((size_t)(b * S_ + q0 + row) * H_ + h) * HD_ + c8;
        cpa16(&Kh[row * TSTR + c8], qh + src);
        cpa16(&Kl[row * TSTR + c8], qlp + src);
    }
    CP_COMMIT(); CP_WAIT0();
    __syncthreads();

    uint32 qfh[4][4], qfl[4][4];
    #pragma unroll
    for (int kc = 0; kc < 4; kc++) {
        int off = (warp * 16 + a_lr) * TSTR + kc * 16 + a_k8;
        ldsm4(qfh[kc][0], qfh[kc][1], qfh[kc][2], qfh[kc][3], &Kh[off]);
        ldsm4(qfl[kc][0], qfl[kc][1], qfl[kc][2], qfl[kc][3], &Kl[off]);
    }
    __syncthreads();

    float octx[8][4];
    #pragma unroll
    for (int i = 0; i < 8; i++)
        #pragma unroll
        for (int j = 0; j < 4; j++) octx[i][j] = 0.f;
    float m0 = NEG_BIG, m1 = NEG_BIG, l0 = 0.f, l1 = 0.f;

    for (int kt0 = 0; kt0 <= q0; kt0 += 64) {
        // ---- K/V tiles via cp.async ----
        #pragma unroll
        for (int it = 0; it < 4; it++) {
            int f = it * 128 + tid;
            int row = f >> 3, c8 = (f & 7) << 3;
            size_t src = ((size_t)(b * S_ + kt0 + row) * G_ + g) * HD_ + c8;
            cpa16(&Kh[row * TSTR + c8], kh + src);
            cpa16(&Kl[row * TSTR + c8], kl + src);
            cpa16(&Vh[row * TSTR + c8], vh + src);
            cpa16(&Vl[row * TSTR + c8], vl + src);
        }
        CP_COMMIT(); CP_WAIT0();
        __syncthreads();

        // ---- Scores ----
        float sc[8][4];
        #pragma unroll
        for (int i = 0; i < 8; i++)
            #pragma unroll
            for (int j = 0; j < 4; j++) sc[i][j] = 0.f;

        #pragma unroll
        for (int kg = 0; kg < 4; kg++) {
            #pragma unroll
            for (int kc = 0; kc < 4; kc++) {
                uint32 bh0, bh1, bh2, bh3, bl0, bl1, bl2, bl3;
                int off = (kg * 16 + b_nr) * TSTR + kc * 16 + b_k8;
                ldsm4(bh0, bh1, bh2, bh3, &Kh[off]);
                ldsm4(bl0, bl1, bl2, bl3, &Kl[off]);
                mma16816(sc[2*kg],   qfh[kc], bh0, bh1);
                mma16816(sc[2*kg],   qfl[kc], bh0, bh1);
                mma16816(sc[2*kg],   qfh[kc], bl0, bl1);
                mma16816(sc[2*kg+1], qfh[kc], bh2, bh3);
                mma16816(sc[2*kg+1], qfl[kc], bh2, bh3);
                mma16816(sc[2*kg+1], qfh[kc], bl2, bl3);
            }
        }

        const int gq = lane >> 2, tt = lane & 3;
        if (kt0 == q0) {
            int qi0 = q0 + warp * 16 + gq;
            int qi1 = qi0 + 8;
            #pragma unroll
            for (int j = 0; j < 8; j++) {
                int kj = kt0 + j * 8 + tt * 2;
                if (kj     > qi0) sc[j][0] = NEG_BIG;
                if (kj + 1 > qi0) sc[j][1] = NEG_BIG;
                if (kj     > qi1) sc[j][2] = NEG_BIG;
                if (kj + 1 > qi1) sc[j][3] = NEG_BIG;
            }
        }

        // ---- Online softmax ----
        float mx0 = NEG_BIG, mx1 = NEG_BIG;
        #pragma unroll
        for (int j = 0; j < 8; j++) {
            mx0 = fmaxf(mx0, fmaxf(sc[j][0], sc[j][1]));
            mx1 = fmaxf(mx1, fmaxf(sc[j][2], sc[j][3]));
        }
        #pragma unroll
        for (int o = 1; o <= 2; o <<= 1) {
            mx0 = fmaxf(mx0, __shfl_xor_sync(0xffffffffu, mx0, o));
            mx1 = fmaxf(mx1, __shfl_xor_sync(0xffffffffu, mx1, o));
        }
        mx0 = fmaxf(mx0, m0); mx1 = fmaxf(mx1, m1);
        float alpha0 = __expf(m0 - mx0), alpha1 = __expf(m1 - mx1);
        m0 = mx0; m1 = mx1;

        float s0 = 0.f, s1 = 0.f;
        #pragma unroll
        for (int j = 0; j < 8; j++) {
            sc[j][0] = __expf(sc[j][0] - m0); s0 += sc[j][0];
            sc[j][1] = __expf(sc[j][1] - m0); s0 += sc[j][1];
            sc[j][2] = __expf(sc[j][2] - m1); s1 += sc[j][2];
            sc[j][3] = __expf(sc[j][3] - m1); s1 += sc[j][3];
        }
        #pragma unroll
        for (int o = 1; o <= 2; o <<= 1) {
            s0 += __shfl_xor_sync(0xffffffffu, s0, o);
            s1 += __shfl_xor_sync(0xffffffffu, s1, o);
        }
        l0 = l0 * alpha0 + s0;
        l1 = l1 * alpha1 + s1;

        #pragma unroll
        for (int ni = 0; ni < 8; ni++) {
            octx[ni][0] *= alpha0; octx[ni][1] *= alpha0;
            octx[ni][2] *= alpha1; octx[ni][3] *= alpha1;
        }

        // ---- P fragments from score fragments ----
        uint32 aph[4][4], apl[4][4];
        #pragma unroll
        for (int kc = 0; kc < 4; kc++) {
            split2(sc[2*kc][0],   sc[2*kc][1],   aph[kc][0], apl[kc][0]);
            split2(sc[2*kc][2],   sc[2*kc][3],   aph[kc][1], apl[kc][1]);
            split2(sc[2*kc+1][0], sc[2*kc+1][1], aph[kc][2], apl[kc][2]);
            split2(sc[2*kc+1][2], sc[2*kc+1][3], aph[kc][3], apl[kc][3]);
        }

        // ---- ctx += P @ V ----
        #pragma unroll
        for (int ni = 0; ni < 8; ni++) {
            #pragma unroll
            for (int kc = 0; kc < 4; kc++) {
                uint32 vh0, vh1, vl0, vl1;
                int off = (kc * 16 + v_r) * TSTR + ni * 8;
                ldsm2t(vh0, vh1, &Vh[off]);
                ldsm2t(vl0, vl1, &Vl[off]);
                mma16816(octx[ni], aph[kc], vh0, vh1);
                mma16816(octx[ni], aph[kc], vl0, vl1);
                mma16816(octx[ni], apl[kc], vh0, vh1);
            }
        }
        __syncthreads();
    }

    // ---- Epilogue: normalize, split to bf16 hi/lo, write ----
    const int gq = lane >> 2, tt = lane & 3;
    float inv0 = 1.0f / l0, inv1 = 1.0f / l1;
    #pragma unroll
    for (int ni = 0; ni < 8; ni++) {
        int row = q0 + warp * 16 + gq;
        int col = ni * 8 + tt * 2;
        size_t d0 = ((size_t)(b * S_ + row) * H_ + h) * HD_ + col;
        size_t d1 = ((size_t)(b * S_ + row + 8) * H_ + h) * HD_ + col;
        uint32 hp, lp;
        split2(octx[ni][0] * inv0, octx[ni][1] * inv0, hp, lp);
        *(uint32*)(ch + d0) = hp; *(uint32*)(cl + d0) = lp;
        split2(octx[ni][2] * inv1, octx[ni][3] * inv1, hp, lp);
        *(uint32*)(ch + d1) = hp; *(uint32*)(cl + d1) = lp;
    }
}

// ---------------------------------------------------------------------------
// Launch
// ---------------------------------------------------------------------------
extern "C" void kernel_launch(void* const* d_in, const int* in_sizes, int n_in,
                              void* d_out, int out_size)
{
    (void)in_sizes; (void)n_in; (void)out_size;
    const float* x    = (const float*)d_in[0];
    const float* cosp = (const float*)d_in[2];
    const float* sinp = (const float*)d_in[3];
    const float* Wq   = (const float*)d_in[4];
    const float* Wk   = (const float*)d_in[5];
    const float* Wv   = (const float*)d_in[6];
    const float* Wo   = (const float*)d_in[7];
    const float* qsc  = (const float*)d_in[8];
    const float* ksc  = (const float*)d_in[9];
    float* out = (float*)d_out;

    float *pqf, *pkf, *pvf;
    __nv_bfloat16 *pxh, *pxl, *pwqh, *pwql, *pwkh, *pwkl, *pwvh, *pwvl,
                  *pwoh, *pwol, *pqh, *pql, *pkh, *pkl, *pvh, *pvl, *pch, *pcl;
    cudaGetSymbolAddress((void**)&pqf, g_qf);
    cudaGetSymbolAddress((void**)&pkf, g_kf);
    cudaGetSymbolAddress((void**)&pvf, g_vf);
    cudaGetSymbolAddress((void**)&pxh, g_xh);   cudaGetSymbolAddress((void**)&pxl, g_xl);
    cudaGetSymbolAddress((void**)&pwqh, g_wqh); cudaGetSymbolAddress((void**)&pwql, g_wql);
    cudaGetSymbolAddress((void**)&pwkh, g_wkh); cudaGetSymbolAddress((void**)&pwkl, g_wkl);
    cudaGetSymbolAddress((void**)&pwvh, g_wvh); cudaGetSymbolAddress((void**)&pwvl, g_wvl);
    cudaGetSymbolAddress((void**)&pwoh, g_woh); cudaGetSymbolAddress((void**)&pwol, g_wol);
    cudaGetSymbolAddress((void**)&pqh, g_qh);   cudaGetSymbolAddress((void**)&pql, g_ql);
    cudaGetSymbolAddress((void**)&pkh, g_kh);   cudaGetSymbolAddress((void**)&pkl, g_kl);
    cudaGetSymbolAddress((void**)&pvh, g_vh);   cudaGetSymbolAddress((void**)&pvl, g_vl);
    cudaGetSymbolAddress((void**)&pch, g_ch);   cudaGetSymbolAddress((void**)&pcl, g_cl);

    // split inputs/weights to bf16 hi/lo
    split_f32<<<(M_*D_/4 + 255)/256, 256>>>(x,  pxh,  pxl,  M_*D_/4);
    split_f32<<<(H_*HD_*D_/4 + 255)/256, 256>>>(Wq, pwqh, pwql, H_*HD_*D_/4);
    split_f32<<<(G_*HD_*D_/4 + 255)/256, 256>>>(Wk, pwkh, pwkl, G_*HD_*D_/4);
    split_f32<<<(G_*HD_*D_/4 + 255)/256, 256>>>(Wv, pwvh, pwvl, G_*HD_*D_/4);
    split_f32<<<(D_*H_*HD_/4 + 255)/256, 256>>>(Wo, pwoh, pwol, D_*H_*HD_/4);

    // merged QKV projection
    gemm_qkv<<<dim3(48, M_/BM), 256>>>();

    // rmsnorm + rope -> bf16 hi/lo
    rms_rope_split<<<(M_*H_)/8, 256>>>(pqf, pqh, pql, cosp, sinp, qsc, H_, 0.125f);
    rms_rope_split<<<(M_*G_)/8, 256>>>(pkf, pkh, pkl, cosp, sinp, ksc, G_, 1.0f);
    split_f32<<<(M_*G_*HD_/4 + 255)/256, 256>>>(pvf, pvh, pvl, M_*G_*HD_/4);

    // attention -> ctx bf16 hi/lo
    attn_tc<<<dim3(S_/64, H_, B_), 128>>>(pqh, pql, pkh, pkl, pvh, pvl, pch, pcl);

    // output projection
    gemm_o<<<dim3(D_/BN, M_/BM), 256>>>(out);
}

// round 7
// speedup vs baseline: 1.1046x; 1.1046x over previous
#include <cuda_runtime.h>
#include <cuda_bf16.h>
#include <math.h>

#define B_ 2
#define S_ 2048
#define D_ 2048
#define H_ 32
#define G_ 8
#define HD_ 64
#define GS_ (H_/G_)
#define M_ (B_*S_)

typedef unsigned int uint32;

// ---- tensor-core helpers ----
__device__ __forceinline__ void ldsm4(uint32 &r0, uint32 &r1, uint32 &r2, uint32 &r3,
                                      const void* p) {
    uint32 a = (uint32)__cvta_generic_to_shared(p);
    asm volatile("ldmatrix.sync.aligned.m8n8.x4.shared.b16 {%0,%1,%2,%3},[%4];"
                 : "=r"(r0), "=r"(r1), "=r"(r2), "=r"(r3) : "r"(a));
}
__device__ __forceinline__ void ldsm2t(uint32 &r0, uint32 &r1, const void* p) {
    uint32 a = (uint32)__cvta_generic_to_shared(p);
    asm volatile("ldmatrix.sync.aligned.m8n8.x2.trans.shared.b16 {%0,%1},[%2];"
                 : "=r"(r0), "=r"(r1) : "r"(a));
}
__device__ __forceinline__ void mma16816(float c[4], const uint32 a[4],
                                         uint32 b0, uint32 b1) {
    asm volatile(
        "mma.sync.aligned.m16n8k16.row.col.f32.bf16.bf16.f32 "
        "{%0,%1,%2,%3},{%4,%5,%6,%7},{%8,%9},{%0,%1,%2,%3};"
        : "+f"(c[0]), "+f"(c[1]), "+f"(c[2]), "+f"(c[3])
        : "r"(a[0]), "r"(a[1]), "r"(a[2]), "r"(a[3]), "r"(b0), "r"(b1));
}
// split two fp32 into packed bf16 hi + packed bf16 lo (p0 in low half)
__device__ __forceinline__ void split2(float p0, float p1, uint32 &h, uint32 &l) {
    asm("cvt.rn.bf16x2.f32 %0, %1, %2;" : "=r"(h) : "f"(p1), "f"(p0));
    float r0 = __uint_as_float(h << 16);
    float r1 = __uint_as_float(h & 0xffff0000u);
    asm("cvt.rn.bf16x2.f32 %0, %1, %2;" : "=r"(l) : "f"(p1 - r1), "f"(p0 - r0));
}
__device__ __forceinline__ void cvt4(float4 v, uint2 &hi, uint2 &lo) {
    split2(v.x, v.y, hi.x, lo.x);
    split2(v.z, v.w, hi.y, lo.y);
}

// Scratch
__device__ float g_q[(size_t)M_*H_*HD_];
__device__ float g_k[(size_t)M_*G_*HD_];
__device__ float g_v[(size_t)M_*G_*HD_];
__device__ float g_ctx[(size_t)M_*H_*HD_];

// ---------------------------------------------------------------------------
// NT GEMM, bf16-split tensor cores, DOUBLE-BUFFERED smem, 1 sync per k-block.
// CTA tile 128x64x32, 256 threads, warp tile 32x32. fp32 in/out.
// ---------------------------------------------------------------------------
#define BM 128
#define BN 64
#define BKK 32
#define ASTR 40
#define STAGE_ELEMS (BM*ASTR*2 + BN*ASTR*2)   // Ah+Al+Bh+Bl = 15360 elems
#define SMEM_BYTES  (2 * STAGE_ELEMS * 2)      // 2 stages * 2B = 61440

__device__ __forceinline__ void gemm_body(
    const float* __restrict__ A, const float* __restrict__ Bm,
    float* __restrict__ C, int N, int K, int m0, int n0, __nv_bfloat16* sm)
{
    const int tid  = threadIdx.x;
    const int lane = tid & 31;
    const int warp = tid >> 5;
    const int wm = (warp >> 1) * 32;
    const int wn = (warp & 1) * 32;

    const int a_lr = lane & 15;
    const int a_k8 = ((lane >> 4) & 1) << 3;
    const int b_nr = (((lane >> 4) & 1) << 3) | (lane & 7);
    const int b_k8 = ((lane >> 3) & 1) << 3;

    float acc[2][4][4];
    #pragma unroll
    for (int i = 0; i < 2; i++)
        #pragma unroll
        for (int j = 0; j < 4; j++)
            #pragma unroll
            for (int t = 0; t < 4; t++) acc[i][j][t] = 0.f;

    // register staging: A 128x32 fp32 = 1024 float4 (4/thread), B 64x32 = 512 (2/thread)
    float4 ar[4], br[2];
    #pragma unroll
    for (int it = 0; it < 4; it++) {
        int f = it * 256 + tid, row = f >> 3, c4 = f & 7;
        ar[it] = *(const float4*)(A + (size_t)(m0 + row) * K + c4 * 4);
    }
    #pragma unroll
    for (int it = 0; it < 2; it++) {
        int f = it * 256 + tid, row = f >> 3, c4 = f & 7;
        br[it] = *(const float4*)(Bm + (size_t)(n0 + row) * K + c4 * 4);
    }

    for (int kb = 0; kb < K; kb += BKK) {
        const int st = (kb >> 5) & 1;
        __nv_bfloat16* Ah = sm + st * STAGE_ELEMS;
        __nv_bfloat16* Al = Ah + BM * ASTR;
        __nv_bfloat16* Bh = Al + BM * ASTR;
        __nv_bfloat16* Bl = Bh + BN * ASTR;

        // store staged regs -> this stage (fp32 -> bf16 hi/lo)
        #pragma unroll
        for (int it = 0; it < 4; it++) {
            int f = it * 256 + tid, row = f >> 3, c4 = f & 7;
            uint2 hi, lo; cvt4(ar[it], hi, lo);
            *(uint2*)&Ah[row * ASTR + c4 * 4] = hi;
            *(uint2*)&Al[row * ASTR + c4 * 4] = lo;
        }
        #pragma unroll
        for (int it = 0; it < 2; it++) {
            int f = it * 256 + tid, row = f >> 3, c4 = f & 7;
            uint2 hi, lo; cvt4(br[it], hi, lo);
            *(uint2*)&Bh[row * ASTR + c4 * 4] = hi;
            *(uint2*)&Bl[row * ASTR + c4 * 4] = lo;
        }
        __syncthreads();   // the ONLY barrier per k-block

        // prefetch next tile into regs (overlaps the MMAs below)
        if (kb + BKK < K) {
            #pragma unroll
            for (int it = 0; it < 4; it++) {
                int f = it * 256 + tid, row = f >> 3, c4 = f & 7;
                ar[it] = *(const float4*)(A + (size_t)(m0 + row) * K + kb + BKK + c4 * 4);
            }
            #pragma unroll
            for (int it = 0; it < 2; it++) {
                int f = it * 256 + tid, row = f >> 3, c4 = f & 7;
                br[it] = *(const float4*)(Bm + (size_t)(n0 + row) * K + kb + BKK + c4 * 4);
            }
        }

        #pragma unroll
        for (int ks = 0; ks < BKK; ks += 16) {
            uint32 ah[2][4], al[2][4], bh[2][4], bl[2][4];
            #pragma unroll
            for (int mi = 0; mi < 2; mi++) {
                int off = (wm + mi * 16 + a_lr) * ASTR + ks + a_k8;
                ldsm4(ah[mi][0], ah[mi][1], ah[mi][2], ah[mi][3], &Ah[off]);
                ldsm4(al[mi][0], al[mi][1], al[mi][2], al[mi][3], &Al[off]);
            }
            #pragma unroll
            for (int p = 0; p < 2; p++) {
                int off = (wn + p * 16 + b_nr) * ASTR + ks + b_k8;
                ldsm4(bh[p][0], bh[p][1], bh[p][2], bh[p][3], &Bh[off]);
                ldsm4(bl[p][0], bl[p][1], bl[p][2], bl[p][3], &Bl[off]);
            }
            #pragma unroll
            for (int mi = 0; mi < 2; mi++)
                #pragma unroll
                for (int ni = 0; ni < 4; ni++) {
                    int p = ni >> 1, s = (ni & 1) * 2;
                    mma16816(acc[mi][ni], ah[mi], bh[p][s], bh[p][s+1]);
                    mma16816(acc[mi][ni], ah[mi], bl[p][s], bl[p][s+1]);
                    mma16816(acc[mi][ni], al[mi], bh[p][s], bh[p][s+1]);
                }
        }
        // no trailing sync: next iteration writes the OTHER stage
    }

    const int gq = lane >> 2, t = lane & 3;
    #pragma unroll
    for (int mi = 0; mi < 2; mi++)
        #pragma unroll
        for (int ni = 0; ni < 4; ni++) {
            int row = m0 + wm + mi * 16 + gq;
            int col = n0 + wn + ni * 8 + t * 2;
            *(float2*)(C + (size_t)row * N + col)       = make_float2(acc[mi][ni][0], acc[mi][ni][1]);
            *(float2*)(C + (size_t)(row + 8) * N + col) = make_float2(acc[mi][ni][2], acc[mi][ni][3]);
        }
}

// merged QKV projection: 48 n-blocks = 32 (Wq) + 8 (Wk) + 8 (Wv)
__global__ __launch_bounds__(256) void gemm_qkv(
    const float* __restrict__ x, const float* __restrict__ Wq,
    const float* __restrict__ Wk, const float* __restrict__ Wv)
{
    extern __shared__ __nv_bfloat16 sm[];
    int nb = blockIdx.x;
    const float* Bm; float* C; int N, n0;
    if (nb < 32)      { Bm = Wq; C = g_q; N = H_*HD_; n0 = nb * 64; }
    else if (nb < 40) { Bm = Wk; C = g_k; N = G_*HD_; n0 = (nb - 32) * 64; }
    else              { Bm = Wv; C = g_v; N = G_*HD_; n0 = (nb - 40) * 64; }
    gemm_body(x, Bm, C, N, D_, blockIdx.y * BM, n0, sm);
}

__global__ __launch_bounds__(256) void gemm_o(
    const float* __restrict__ Wo, float* __restrict__ out)
{
    extern __shared__ __nv_bfloat16 sm[];
    gemm_body(g_ctx, Wo, out, D_, H_*HD_, blockIdx.y * BM, blockIdx.x * 64, sm);
}

// ---------------------------------------------------------------------------
// Fused RMSNorm + RoPE + scalar multiply. One warp per row of 64.
// ---------------------------------------------------------------------------
__global__ __launch_bounds__(256) void rms_rope(
    float* __restrict__ t, const float* __restrict__ cosp,
    const float* __restrict__ sinp, const float* __restrict__ scale,
    int NH, float mul)
{
    const int warp = (blockIdx.x * blockDim.x + threadIdx.x) >> 5;
    const int lane = threadIdx.x & 31;
    const int s = (warp / NH) % S_;
    float* p = t + (size_t)warp * HD_;

    float t1 = p[lane];
    float t2 = p[lane + 32];
    float ss = t1 * t1 + t2 * t2;
    #pragma unroll
    for (int o = 16; o > 0; o >>= 1) ss += __shfl_xor_sync(0xffffffffu, ss, o);
    float rs = rsqrtf(ss * (1.0f / HD_) + 1e-6f);

    float n1 = t1 * rs * (1.0f + scale[lane]);
    float n2 = t2 * rs * (1.0f + scale[lane + 32]);

    float c1 = cosp[s * HD_ + lane],      c2 = cosp[s * HD_ + lane + 32];
    float s1 = sinp[s * HD_ + lane],      s2 = sinp[s * HD_ + lane + 32];
    float o1 = (n1 * c1 - n2 * s1) * mul;
    float o2 = (n2 * c2 + n1 * s2) * mul;
    p[lane]      = o1;
    p[lane + 32] = o2;
}

// ---------------------------------------------------------------------------
// Tensor-core causal flash attention (bf16-split, FA2-style) — R4 validated.
// ---------------------------------------------------------------------------
#define TSTR 72
#define NEG_BIG (-1e30f)

__global__ __launch_bounds__(128) void attn_tc(
    const float* __restrict__ q, const float* __restrict__ k,
    const float* __restrict__ v, float* __restrict__ ctx)
{
    __shared__ __align__(16) __nv_bfloat16 Kh[64*TSTR];
    __shared__ __align__(16) __nv_bfloat16 Kl[64*TSTR];
    __shared__ __align__(16) __nv_bfloat16 Vh[64*TSTR];
    __shared__ __align__(16) __nv_bfloat16 Vl[64*TSTR];

    const int tid  = threadIdx.x;
    const int lane = tid & 31;
    const int warp = tid >> 5;
    const int qt = blockIdx.x, h = blockIdx.y, b = blockIdx.z;
    const int g  = h / GS_;
    const int q0 = qt * 64;

    const int a_lr = lane & 15;
    const int a_k8 = ((lane >> 4) & 1) << 3;
    const int b_nr = (((lane >> 4) & 1) << 3) | (lane & 7);
    const int b_k8 = ((lane >> 3) & 1) << 3;
    const int v_r  = lane & 15;

    #pragma unroll
    for (int it = 0; it < 8; it++) {
        int f = it * 128 + tid, row = f >> 4, c4 = f & 15;
        float4 val = *(const float4*)(q + (((size_t)(b * S_ + q0 + row)) * H_ + h) * HD_ + c4 * 4);
        uint2 hi, lo; cvt4(val, hi, lo);
        *(uint2*)&Kh[row * TSTR + c4 * 4] = hi;
        *(uint2*)&Kl[row * TSTR + c4 * 4] = lo;
    }
    __syncthreads();

    uint32 qh[4][4], ql[4][4];
    #pragma unroll
    for (int kc = 0; kc < 4; kc++) {
        int off = (warp * 16 + a_lr) * TSTR + kc * 16 + a_k8;
        ldsm4(qh[kc][0], qh[kc][1], qh[kc][2], qh[kc][3], &Kh[off]);
        ldsm4(ql[kc][0], ql[kc][1], ql[kc][2], ql[kc][3], &Kl[off]);
    }
    __syncthreads();

    float octx[8][4];
    #pragma unroll
    for (int i = 0; i < 8; i++)
        #pragma unroll
        for (int j = 0; j < 4; j++) octx[i][j] = 0.f;
    float m0 = NEG_BIG, m1 = NEG_BIG, l0 = 0.f, l1 = 0.f;

    for (int kt0 = 0; kt0 <= q0; kt0 += 64) {
        #pragma unroll
        for (int it = 0; it < 8; it++) {
            int f = it * 128 + tid, row = f >> 4, c4 = f & 15;
            size_t base = (((size_t)(b * S_ + kt0 + row)) * G_ + g) * HD_ + c4 * 4;
            uint2 hi, lo;
            cvt4(*(const float4*)(k + base), hi, lo);
            *(uint2*)&Kh[row * TSTR + c4 * 4] = hi;
            *(uint2*)&Kl[row * TSTR + c4 * 4] = lo;
            cvt4(*(const float4*)(v + base), hi, lo);
            *(uint2*)&Vh[row * TSTR + c4 * 4] = hi;
            *(uint2*)&Vl[row * TSTR + c4 * 4] = lo;
        }
        __syncthreads();

        float sc[8][4];
        #pragma unroll
        for (int i = 0; i < 8; i++)
            #pragma unroll
            for (int j = 0; j < 4; j++) sc[i][j] = 0.f;

        #pragma unroll
        for (int kg = 0; kg < 4; kg++) {
            #pragma unroll
            for (int kc = 0; kc < 4; kc++) {
                uint32 bh0, bh1, bh2, bh3, bl0, bl1, bl2, bl3;
                int off = (kg * 16 + b_nr) * TSTR + kc * 16 + b_k8;
                ldsm4(bh0, bh1, bh2, bh3, &Kh[off]);
                ldsm4(bl0, bl1, bl2, bl3, &Kl[off]);
                mma16816(sc[2*kg],   qh[kc], bh0, bh1);
                mma16816(sc[2*kg],   ql[kc], bh0, bh1);
                mma16816(sc[2*kg],   qh[kc], bl0, bl1);
                mma16816(sc[2*kg+1], qh[kc], bh2, bh3);
                mma16816(sc[2*kg+1], ql[kc], bh2, bh3);
                mma16816(sc[2*kg+1], qh[kc], bl2, bl3);
            }
        }

        const int gq = lane >> 2, tt = lane & 3;
        if (kt0 == q0) {
            int qi0 = q0 + warp * 16 + gq;
            int qi1 = qi0 + 8;
            #pragma unroll
            for (int j = 0; j < 8; j++) {
                int kj = kt0 + j * 8 + tt * 2;
                if (kj     > qi0) sc[j][0] = NEG_BIG;
                if (kj + 1 > qi0) sc[j][1] = NEG_BIG;
                if (kj     > qi1) sc[j][2] = NEG_BIG;
                if (kj + 1 > qi1) sc[j][3] = NEG_BIG;
            }
        }

        float mx0 = NEG_BIG, mx1 = NEG_BIG;
        #pragma unroll
        for (int j = 0; j < 8; j++) {
            mx0 = fmaxf(mx0, fmaxf(sc[j][0], sc[j][1]));
            mx1 = fmaxf(mx1, fmaxf(sc[j][2], sc[j][3]));
        }
        #pragma unroll
        for (int o = 1; o <= 2; o <<= 1) {
            mx0 = fmaxf(mx0, __shfl_xor_sync(0xffffffffu, mx0, o));
            mx1 = fmaxf(mx1, __shfl_xor_sync(0xffffffffu, mx1, o));
        }
        mx0 = fmaxf(mx0, m0); mx1 = fmaxf(mx1, m1);
        float alpha0 = __expf(m0 - mx0), alpha1 = __expf(m1 - mx1);
        m0 = mx0; m1 = mx1;

        float s0 = 0.f, s1 = 0.f;
        #pragma unroll
        for (int j = 0; j < 8; j++) {
            sc[j][0] = __expf(sc[j][0] - m0); s0 += sc[j][0];
            sc[j][1] = __expf(sc[j][1] - m0); s0 += sc[j][1];
            sc[j][2] = __expf(sc[j][2] - m1); s1 += sc[j][2];
            sc[j][3] = __expf(sc[j][3] - m1); s1 += sc[j][3];
        }
        #pragma unroll
        for (int o = 1; o <= 2; o <<= 1) {
            s0 += __shfl_xor_sync(0xffffffffu, s0, o);
            s1 += __shfl_xor_sync(0xffffffffu, s1, o);
        }
        l0 = l0 * alpha0 + s0;
        l1 = l1 * alpha1 + s1;

        #pragma unroll
        for (int ni = 0; ni < 8; ni++) {
            octx[ni][0] *= alpha0; octx[ni][1] *= alpha0;
            octx[ni][2] *= alpha1; octx[ni][3] *= alpha1;
        }

        uint32 aph[4][4], apl[4][4];
        #pragma unroll
        for (int kc = 0; kc < 4; kc++) {
            split2(sc[2*kc][0],   sc[2*kc][1],   aph[kc][0], apl[kc][0]);
            split2(sc[2*kc][2],   sc[2*kc][3],   aph[kc][1], apl[kc][1]);
            split2(sc[2*kc+1][0], sc[2*kc+1][1], aph[kc][2], apl[kc][2]);
            split2(sc[2*kc+1][2], sc[2*kc+1][3], aph[kc][3], apl[kc][3]);
        }

        #pragma unroll
        for (int ni = 0; ni < 8; ni++) {
            #pragma unroll
            for (int kc = 0; kc < 4; kc++) {
                uint32 vh0, vh1, vl0, vl1;
                int off = (kc * 16 + v_r) * TSTR + ni * 8;
                ldsm2t(vh0, vh1, &Vh[off]);
                ldsm2t(vl0, vl1, &Vl[off]);
                mma16816(octx[ni], aph[kc], vh0, vh1);
                mma16816(octx[ni], aph[kc], vl0, vl1);
                mma16816(octx[ni], apl[kc], vh0, vh1);
            }
        }
        __syncthreads();
    }

    const int gq = lane >> 2, tt = lane & 3;
    float inv0 = 1.0f / l0, inv1 = 1.0f / l1;
    #pragma unroll
    for (int ni = 0; ni < 8; ni++) {
        int row = q0 + warp * 16 + gq;
        int col = ni * 8 + tt * 2;
        *(float2*)(ctx + (((size_t)(b * S_ + row)) * H_ + h) * HD_ + col) =
            make_float2(octx[ni][0] * inv0, octx[ni][1] * inv0);
        *(float2*)(ctx + (((size_t)(b * S_ + row + 8)) * H_ + h) * HD_ + col) =
            make_float2(octx[ni][2] * inv1, octx[ni][3] * inv1);
    }
}

// ---------------------------------------------------------------------------
// Launch
// ---------------------------------------------------------------------------
extern "C" void kernel_launch(void* const* d_in, const int* in_sizes, int n_in,
                              void* d_out, int out_size)
{
    (void)in_sizes; (void)n_in; (void)out_size;
    const float* x    = (const float*)d_in[0];
    const float* cosp = (const float*)d_in[2];
    const float* sinp = (const float*)d_in[3];
    const float* Wq   = (const float*)d_in[4];
    const float* Wk   = (const float*)d_in[5];
    const float* Wv   = (const float*)d_in[6];
    const float* Wo   = (const float*)d_in[7];
    const float* qsc  = (const float*)d_in[8];
    const float* ksc  = (const float*)d_in[9];
    float* out = (float*)d_out;

    float *pq, *pk, *pv, *pc;
    cudaGetSymbolAddress((void**)&pq, g_q);
    cudaGetSymbolAddress((void**)&pk, g_k);
    cudaGetSymbolAddress((void**)&pv, g_v);
    cudaGetSymbolAddress((void**)&pc, g_ctx);

    static bool attr_done = false;
    if (!attr_done) {
        cudaFuncSetAttribute(gemm_qkv, cudaFuncAttributeMaxDynamicSharedMemorySize, SMEM_BYTES);
        cudaFuncSetAttribute(gemm_o,   cudaFuncAttributeMaxDynamicSharedMemorySize, SMEM_BYTES);
        attr_done = true;
    }

    // merged QKV projection (double-buffered)
    gemm_qkv<<<dim3(48, M_/BM), 256, SMEM_BYTES>>>(x, Wq, Wk, Wv);

    // rmsnorm + rope
    rms_rope<<<(M_*H_)/8, 256>>>(pq, cosp, sinp, qsc, H_, 0.125f);
    rms_rope<<<(M_*G_)/8, 256>>>(pk, cosp, sinp, ksc, G_, 1.0f);

    // attention
    attn_tc<<<dim3(S_/64, H_, B_), 128>>>(pq, pk, pv, pc);

    // output projection
    gemm_o<<<dim3(D_/BN, M_/BM), 256, SMEM_BYTES>>>(Wo, out);
}

// round 9
// speedup vs baseline: 1.4353x; 1.2994x over previous
#include <cuda_runtime.h>
#include <cuda_fp16.h>
#include <math.h>

#define B_ 2
#define S_ 2048
#define D_ 2048
#define H_ 32
#define G_ 8
#define HD_ 64
#define GS_ (H_/G_)
#define M_ (B_*S_)

typedef unsigned int uint32;

// ---- tensor-core helpers (fp16 path) ----
__device__ __forceinline__ void ldsm4(uint32 &r0, uint32 &r1, uint32 &r2, uint32 &r3,
                                      const void* p) {
    uint32 a = (uint32)__cvta_generic_to_shared(p);
    asm volatile("ldmatrix.sync.aligned.m8n8.x4.shared.b16 {%0,%1,%2,%3},[%4];"
                 : "=r"(r0), "=r"(r1), "=r"(r2), "=r"(r3) : "r"(a));
}
__device__ __forceinline__ void ldsm2t(uint32 &r0, uint32 &r1, const void* p) {
    uint32 a = (uint32)__cvta_generic_to_shared(p);
    asm volatile("ldmatrix.sync.aligned.m8n8.x2.trans.shared.b16 {%0,%1},[%2];"
                 : "=r"(r0), "=r"(r1) : "r"(a));
}
__device__ __forceinline__ void mma16816h(float c[4], const uint32 a[4],
                                          uint32 b0, uint32 b1) {
    asm volatile(
        "mma.sync.aligned.m16n8k16.row.col.f32.f16.f16.f32 "
        "{%0,%1,%2,%3},{%4,%5,%6,%7},{%8,%9},{%0,%1,%2,%3};"
        : "+f"(c[0]), "+f"(c[1]), "+f"(c[2]), "+f"(c[3])
        : "r"(a[0]), "r"(a[1]), "r"(a[2]), "r"(a[3]), "r"(b0), "r"(b1));
}
// split two fp32 into packed fp16 hi + packed fp16 lo (p0 in low half)
__device__ __forceinline__ void split2h(float p0, float p1, uint32 &h, uint32 &l) {
    __half2 hh = __floats2half2_rn(p0, p1);
    float2 hf = __half22float2(hh);
    __half2 ll = __floats2half2_rn(p0 - hf.x, p1 - hf.y);
    h = *(uint32*)&hh;
    l = *(uint32*)&ll;
}
__device__ __forceinline__ uint32 pack2h(float p0, float p1) {
    __half2 hh = __floats2half2_rn(p0, p1);
    return *(uint32*)&hh;
}
__device__ __forceinline__ void cvt4h(float4 v, uint2 &hi, uint2 &lo) {
    split2h(v.x, v.y, hi.x, lo.x);
    split2h(v.z, v.w, hi.y, lo.y);
}
__device__ __forceinline__ uint2 cvt4h1(float4 v) {
    return make_uint2(pack2h(v.x, v.y), pack2h(v.z, v.w));
}

// Scratch
__device__ float g_q[(size_t)M_*H_*HD_];
__device__ float g_k[(size_t)M_*G_*HD_];
__device__ float g_v[(size_t)M_*G_*HD_];
__device__ float g_ctx[(size_t)M_*H_*HD_];

// ---------------------------------------------------------------------------
// NT GEMM, fp16 2-term split (A = hi+lo fp16, B = fp16), double-buffered.
// C = A@B^T, CTA tile 128x64x32, 256 threads, warp tile 32x32, fp32 io.
// ---------------------------------------------------------------------------
#define BM 128
#define BN 64
#define BKK 32
#define ASTR 40
#define STAGE_ELEMS (BM*ASTR*2 + BN*ASTR)     // Ah+Al+Bh = 12800 halves
#define SMEM_BYTES  (2 * STAGE_ELEMS * 2)      // 2 stages = 51200 B

__device__ __forceinline__ void gemm_body(
    const float* __restrict__ A, const float* __restrict__ Bm,
    float* __restrict__ C, int N, int K, int m0, int n0, __half* sm)
{
    const int tid  = threadIdx.x;
    const int lane = tid & 31;
    const int warp = tid >> 5;
    const int wm = (warp >> 1) * 32;
    const int wn = (warp & 1) * 32;

    const int a_lr = lane & 15;
    const int a_k8 = ((lane >> 4) & 1) << 3;
    const int b_nr = (((lane >> 4) & 1) << 3) | (lane & 7);
    const int b_k8 = ((lane >> 3) & 1) << 3;

    float acc[2][4][4];
    #pragma unroll
    for (int i = 0; i < 2; i++)
        #pragma unroll
        for (int j = 0; j < 4; j++)
            #pragma unroll
            for (int t = 0; t < 4; t++) acc[i][j][t] = 0.f;

    float4 ar[4], br[2];
    #pragma unroll
    for (int it = 0; it < 4; it++) {
        int f = it * 256 + tid, row = f >> 3, c4 = f & 7;
        ar[it] = *(const float4*)(A + (size_t)(m0 + row) * K + c4 * 4);
    }
    #pragma unroll
    for (int it = 0; it < 2; it++) {
        int f = it * 256 + tid, row = f >> 3, c4 = f & 7;
        br[it] = *(const float4*)(Bm + (size_t)(n0 + row) * K + c4 * 4);
    }

    for (int kb = 0; kb < K; kb += BKK) {
        const int st = (kb >> 5) & 1;
        __half* Ah = sm + st * STAGE_ELEMS;
        __half* Al = Ah + BM * ASTR;
        __half* Bh = Al + BM * ASTR;

        #pragma unroll
        for (int it = 0; it < 4; it++) {
            int f = it * 256 + tid, row = f >> 3, c4 = f & 7;
            uint2 hi, lo; cvt4h(ar[it], hi, lo);
            *(uint2*)&Ah[row * ASTR + c4 * 4] = hi;
            *(uint2*)&Al[row * ASTR + c4 * 4] = lo;
        }
        #pragma unroll
        for (int it = 0; it < 2; it++) {
            int f = it * 256 + tid, row = f >> 3, c4 = f & 7;
            *(uint2*)&Bh[row * ASTR + c4 * 4] = cvt4h1(br[it]);
        }
        __syncthreads();   // single barrier per k-block (double buffer)

        if (kb + BKK < K) {
            #pragma unroll
            for (int it = 0; it < 4; it++) {
                int f = it * 256 + tid, row = f >> 3, c4 = f & 7;
                ar[it] = *(const float4*)(A + (size_t)(m0 + row) * K + kb + BKK + c4 * 4);
            }
            #pragma unroll
            for (int it = 0; it < 2; it++) {
                int f = it * 256 + tid, row = f >> 3, c4 = f & 7;
                br[it] = *(const float4*)(Bm + (size_t)(n0 + row) * K + kb + BKK + c4 * 4);
            }
        }

        #pragma unroll
        for (int ks = 0; ks < BKK; ks += 16) {
            uint32 ah[2][4], al[2][4], bh[2][4];
            #pragma unroll
            for (int mi = 0; mi < 2; mi++) {
                int off = (wm + mi * 16 + a_lr) * ASTR + ks + a_k8;
                ldsm4(ah[mi][0], ah[mi][1], ah[mi][2], ah[mi][3], &Ah[off]);
                ldsm4(al[mi][0], al[mi][1], al[mi][2], al[mi][3], &Al[off]);
            }
            #pragma unroll
            for (int p = 0; p < 2; p++) {
                int off = (wn + p * 16 + b_nr) * ASTR + ks + b_k8;
                ldsm4(bh[p][0], bh[p][1], bh[p][2], bh[p][3], &Bh[off]);
            }
            #pragma unroll
            for (int mi = 0; mi < 2; mi++)
                #pragma unroll
                for (int ni = 0; ni < 4; ni++) {
                    int p = ni >> 1, s = (ni & 1) * 2;
                    mma16816h(acc[mi][ni], ah[mi], bh[p][s], bh[p][s+1]);
                    mma16816h(acc[mi][ni], al[mi], bh[p][s], bh[p][s+1]);
                }
        }
    }

    const int gq = lane >> 2, t = lane & 3;
    #pragma unroll
    for (int mi = 0; mi < 2; mi++)
        #pragma unroll
        for (int ni = 0; ni < 4; ni++) {
            int row = m0 + wm + mi * 16 + gq;
            int col = n0 + wn + ni * 8 + t * 2;
            *(float2*)(C + (size_t)row * N + col)       = make_float2(acc[mi][ni][0], acc[mi][ni][1]);
            *(float2*)(C + (size_t)(row + 8) * N + col) = make_float2(acc[mi][ni][2], acc[mi][ni][3]);
        }
}

// merged QKV projection: 48 n-blocks = 32 (Wq) + 8 (Wk) + 8 (Wv)
__global__ __launch_bounds__(256) void gemm_qkv(
    const float* __restrict__ x, const float* __restrict__ Wq,
    const float* __restrict__ Wk, const float* __restrict__ Wv)
{
    extern __shared__ __half sm[];
    int nb = blockIdx.x;
    const float* Bm; float* C; int N, n0;
    if (nb < 32)      { Bm = Wq; C = g_q; N = H_*HD_; n0 = nb * 64; }
    else if (nb < 40) { Bm = Wk; C = g_k; N = G_*HD_; n0 = (nb - 32) * 64; }
    else              { Bm = Wv; C = g_v; N = G_*HD_; n0 = (nb - 40) * 64; }
    gemm_body(x, Bm, C, N, D_, blockIdx.y * BM, n0, sm);
}

__global__ __launch_bounds__(256) void gemm_o(
    const float* __restrict__ Wo, float* __restrict__ out)
{
    extern __shared__ __half sm[];
    gemm_body(g_ctx, Wo, out, D_, H_*HD_, blockIdx.y * BM, blockIdx.x * 64, sm);
}

// ---------------------------------------------------------------------------
// Fused RMSNorm + RoPE + scalar multiply. One warp per row of 64.
// ---------------------------------------------------------------------------
__global__ __launch_bounds__(256) void rms_rope(
    float* __restrict__ t, const float* __restrict__ cosp,
    const float* __restrict__ sinp, const float* __restrict__ scale,
    int NH, float mul)
{
    const int warp = (blockIdx.x * blockDim.x + threadIdx.x) >> 5;
    const int lane = threadIdx.x & 31;
    const int s = (warp / NH) % S_;
    float* p = t + (size_t)warp * HD_;

    float t1 = p[lane];
    float t2 = p[lane + 32];
    float ss = t1 * t1 + t2 * t2;
    #pragma unroll
    for (int o = 16; o > 0; o >>= 1) ss += __shfl_xor_sync(0xffffffffu, ss, o);
    float rs = rsqrtf(ss * (1.0f / HD_) + 1e-6f);

    float n1 = t1 * rs * (1.0f + scale[lane]);
    float n2 = t2 * rs * (1.0f + scale[lane + 32]);

    float c1 = cosp[s * HD_ + lane],      c2 = cosp[s * HD_ + lane + 32];
    float s1 = sinp[s * HD_ + lane],      s2 = sinp[s * HD_ + lane + 32];
    float o1 = (n1 * c1 - n2 * s1) * mul;
    float o2 = (n2 * c2 + n1 * s2) * mul;
    p[lane]      = o1;
    p[lane + 32] = o2;
}

// ---------------------------------------------------------------------------
// Tensor-core causal flash attention, fp16 2-term split:
// Q = qh+ql (fp16), K/V single fp16; P = ph+pl, V single.
// Block = (b, h, 64 q-rows). 4 warps x 16 rows. Key tiles of 64.
// ---------------------------------------------------------------------------
#define TSTR 72
#define NEG_BIG (-1e30f)

__global__ __launch_bounds__(128) void attn_tc(
    const float* __restrict__ q, const float* __restrict__ k,
    const float* __restrict__ v, float* __restrict__ ctx)
{
    __shared__ __align__(16) __half Kh[64*TSTR];   // qh, then K tiles
    __shared__ __align__(16) __half Vh[64*TSTR];   // ql, then V tiles

    const int tid  = threadIdx.x;
    const int lane = tid & 31;
    const int warp = tid >> 5;
    const int qt = blockIdx.x, h = blockIdx.y, b = blockIdx.z;
    const int g  = h / GS_;
    const int q0 = qt * 64;

    const int a_lr = lane & 15;
    const int a_k8 = ((lane >> 4) & 1) << 3;
    const int b_nr = (((lane >> 4) & 1) << 3) | (lane & 7);
    const int b_k8 = ((lane >> 3) & 1) << 3;
    const int v_r  = lane & 15;

    // ---- Q tile: hi into Kh, lo into Vh; fragments to registers ----
    #pragma unroll
    for (int it = 0; it < 8; it++) {
        int f = it * 128 + tid, row = f >> 4, c4 = f & 15;
        float4 val = *(const float4*)(q + (((size_t)(b * S_ + q0 + row)) * H_ + h) * HD_ + c4 * 4);
        uint2 hi, lo; cvt4h(val, hi, lo);
        *(uint2*)&Kh[row * TSTR + c4 * 4] = hi;
        *(uint2*)&Vh[row * TSTR + c4 * 4] = lo;
    }
    __syncthreads();

    uint32 qh[4][4], ql[4][4];
    #pragma unroll
    for (int kc = 0; kc < 4; kc++) {
        int off = (warp * 16 + a_lr) * TSTR + kc * 16 + a_k8;
        ldsm4(qh[kc][0], qh[kc][1], qh[kc][2], qh[kc][3], &Kh[off]);
        ldsm4(ql[kc][0], ql[kc][1], ql[kc][2], ql[kc][3], &Vh[off]);
    }
    __syncthreads();

    float octx[8][4];
    #pragma unroll
    for (int i = 0; i < 8; i++)
        #pragma unroll
        for (int j = 0; j < 4; j++) octx[i][j] = 0.f;
    float m0 = NEG_BIG, m1 = NEG_BIG, l0 = 0.f, l1 = 0.f;

    for (int kt0 = 0; kt0 <= q0; kt0 += 64) {
        // ---- K/V tiles (single fp16 conversion) ----
        #pragma unroll
        for (int it = 0; it < 8; it++) {
            int f = it * 128 + tid, row = f >> 4, c4 = f & 15;
            size_t base = (((size_t)(b * S_ + kt0 + row)) * G_ + g) * HD_ + c4 * 4;
            *(uint2*)&Kh[row * TSTR + c4 * 4] = cvt4h1(*(const float4*)(k + base));
            *(uint2*)&Vh[row * TSTR + c4 * 4] = cvt4h1(*(const float4*)(v + base));
        }
        __syncthreads();

        // ---- Scores: S = (Qh + Ql) K^T ----
        float sc[8][4];
        #pragma unroll
        for (int i = 0; i < 8; i++)
            #pragma unroll
            for (int j = 0; j < 4; j++) sc[i][j] = 0.f;

        #pragma unroll
        for (int kg = 0; kg < 4; kg++) {
            #pragma unroll
            for (int kc = 0; kc < 4; kc++) {
                uint32 bh0, bh1, bh2, bh3;
                int off = (kg * 16 + b_nr) * TSTR + kc * 16 + b_k8;
                ldsm4(bh0, bh1, bh2, bh3, &Kh[off]);
                mma16816h(sc[2*kg],   qh[kc], bh0, bh1);
                mma16816h(sc[2*kg],   ql[kc], bh0, bh1);
                mma16816h(sc[2*kg+1], qh[kc], bh2, bh3);
                mma16816h(sc[2*kg+1], ql[kc], bh2, bh3);
            }
        }

        const int gq = lane >> 2, tt = lane & 3;
        if (kt0 == q0) {
            int qi0 = q0 + warp * 16 + gq;
            int qi1 = qi0 + 8;
            #pragma unroll
            for (int j = 0; j < 8; j++) {
                int kj = kt0 + j * 8 + tt * 2;
                if (kj     > qi0) sc[j][0] = NEG_BIG;
                if (kj + 1 > qi0) sc[j][1] = NEG_BIG;
                if (kj     > qi1) sc[j][2] = NEG_BIG;
                if (kj + 1 > qi1) sc[j][3] = NEG_BIG;
            }
        }

        // ---- Online softmax ----
        float mx0 = NEG_BIG, mx1 = NEG_BIG;
        #pragma unroll
        for (int j = 0; j < 8; j++) {
            mx0 = fmaxf(mx0, fmaxf(sc[j][0], sc[j][1]));
            mx1 = fmaxf(mx1, fmaxf(sc[j][2], sc[j][3]));
        }
        #pragma unroll
        for (int o = 1; o <= 2; o <<= 1) {
            mx0 = fmaxf(mx0, __shfl_xor_sync(0xffffffffu, mx0, o));
            mx1 = fmaxf(mx1, __shfl_xor_sync(0xffffffffu, mx1, o));
        }
        mx0 = fmaxf(mx0, m0); mx1 = fmaxf(mx1, m1);
        float alpha0 = __expf(m0 - mx0), alpha1 = __expf(m1 - mx1);
        m0 = mx0; m1 = mx1;

        float s0 = 0.f, s1 = 0.f;
        #pragma unroll
        for (int j = 0; j < 8; j++) {
            sc[j][0] = __expf(sc[j][0] - m0); s0 += sc[j][0];
            sc[j][1] = __expf(sc[j][1] - m0); s0 += sc[j][1];
            sc[j][2] = __expf(sc[j][2] - m1); s1 += sc[j][2];
            sc[j][3] = __expf(sc[j][3] - m1); s1 += sc[j][3];
        }
        #pragma unroll
        for (int o = 1; o <= 2; o <<= 1) {
            s0 += __shfl_xor_sync(0xffffffffu, s0, o);
            s1 += __shfl_xor_sync(0xffffffffu, s1, o);
        }
        l0 = l0 * alpha0 + s0;
        l1 = l1 * alpha1 + s1;

        #pragma unroll
        for (int ni = 0; ni < 8; ni++) {
            octx[ni][0] *= alpha0; octx[ni][1] *= alpha0;
            octx[ni][2] *= alpha1; octx[ni][3] *= alpha1;
        }

        // ---- P fragments (hi+lo fp16) from score fragments ----
        uint32 aph[4][4], apl[4][4];
        #pragma unroll
        for (int kc = 0; kc < 4; kc++) {
            split2h(sc[2*kc][0],   sc[2*kc][1],   aph[kc][0], apl[kc][0]);
            split2h(sc[2*kc][2],   sc[2*kc][3],   aph[kc][1], apl[kc][1]);
            split2h(sc[2*kc+1][0], sc[2*kc+1][1], aph[kc][2], apl[kc][2]);
            split2h(sc[2*kc+1][2], sc[2*kc+1][3], aph[kc][3], apl[kc][3]);
        }

        // ---- ctx += (Ph + Pl) @ V ----
        #pragma unroll
        for (int ni = 0; ni < 8; ni++) {
            #pragma unroll
            for (int kc = 0; kc < 4; kc++) {
                uint32 vh0, vh1;
                int off = (kc * 16 + v_r) * TSTR + ni * 8;
                ldsm2t(vh0, vh1, &Vh[off]);
                mma16816h(octx[ni], aph[kc], vh0, vh1);
                mma16816h(octx[ni], apl[kc], vh0, vh1);
            }
        }
        __syncthreads();
    }

    // ---- Epilogue ----
    const int gq = lane >> 2, tt = lane & 3;
    float inv0 = 1.0f / l0, inv1 = 1.0f / l1;
    #pragma unroll
    for (int ni = 0; ni < 8; ni++) {
        int row = q0 + warp * 16 + gq;
        int col = ni * 8 + tt * 2;
        *(float2*)(ctx + (((size_t)(b * S_ + row)) * H_ + h) * HD_ + col) =
            make_float2(octx[ni][0] * inv0, octx[ni][1] * inv0);
        *(float2*)(ctx + (((size_t)(b * S_ + row + 8)) * H_ + h) * HD_ + col) =
            make_float2(octx[ni][2] * inv1, octx[ni][3] * inv1);
    }
}

// ---------------------------------------------------------------------------
// Launch
// ---------------------------------------------------------------------------
extern "C" void kernel_launch(void* const* d_in, const int* in_sizes, int n_in,
                              void* d_out, int out_size)
{
    (void)in_sizes; (void)n_in; (void)out_size;
    const float* x    = (const float*)d_in[0];
    const float* cosp = (const float*)d_in[2];
    const float* sinp = (const float*)d_in[3];
    const float* Wq   = (const float*)d_in[4];
    const float* Wk   = (const float*)d_in[5];
    const float* Wv   = (const float*)d_in[6];
    const float* Wo   = (const float*)d_in[7];
    const float* qsc  = (const float*)d_in[8];
    const float* ksc  = (const float*)d_in[9];
    float* out = (float*)d_out;

    float *pq, *pk, *pv, *pc;
    cudaGetSymbolAddress((void**)&pq, g_q);
    cudaGetSymbolAddress((void**)&pk, g_k);
    cudaGetSymbolAddress((void**)&pv, g_v);
    cudaGetSymbolAddress((void**)&pc, g_ctx);

    static bool attr_done = false;
    if (!attr_done) {
        cudaFuncSetAttribute(gemm_qkv, cudaFuncAttributeMaxDynamicSharedMemorySize, SMEM_BYTES);
        cudaFuncSetAttribute(gemm_o,   cudaFuncAttributeMaxDynamicSharedMemorySize, SMEM_BYTES);
        attr_done = true;
    }

    // merged QKV projection
    gemm_qkv<<<dim3(48, M_/BM), 256, SMEM_BYTES>>>(x, Wq, Wk, Wv);

    // rmsnorm + rope
    rms_rope<<<(M_*H_)/8, 256>>>(pq, cosp, sinp, qsc, H_, 0.125f);
    rms_rope<<<(M_*G_)/8, 256>>>(pk, cosp, sinp, ksc, G_, 1.0f);

    // attention
    attn_tc<<<dim3(S_/64, H_, B_), 128>>>(pq, pk, pv, pc);

    // output projection
    gemm_o<<<dim3(D_/BN, M_/BM), 256, SMEM_BYTES>>>(Wo, out);
}

// round 10
// speedup vs baseline: 1.4664x; 1.0217x over previous
#include <cuda_runtime.h>
#include <cuda_fp16.h>
#include <math.h>

#define B_ 2
#define S_ 2048
#define D_ 2048
#define H_ 32
#define G_ 8
#define HD_ 64
#define GS_ (H_/G_)
#define M_ (B_*S_)

typedef unsigned int uint32;

// ---- tensor-core helpers (fp16 path) ----
__device__ __forceinline__ void ldsm4(uint32 &r0, uint32 &r1, uint32 &r2, uint32 &r3,
                                      const void* p) {
    uint32 a = (uint32)__cvta_generic_to_shared(p);
    asm volatile("ldmatrix.sync.aligned.m8n8.x4.shared.b16 {%0,%1,%2,%3},[%4];"
                 : "=r"(r0), "=r"(r1), "=r"(r2), "=r"(r3) : "r"(a));
}
__device__ __forceinline__ void ldsm2t(uint32 &r0, uint32 &r1, const void* p) {
    uint32 a = (uint32)__cvta_generic_to_shared(p);
    asm volatile("ldmatrix.sync.aligned.m8n8.x2.trans.shared.b16 {%0,%1},[%2];"
                 : "=r"(r0), "=r"(r1) : "r"(a));
}
__device__ __forceinline__ void mma16816h(float c[4], const uint32 a[4],
                                          uint32 b0, uint32 b1) {
    asm volatile(
        "mma.sync.aligned.m16n8k16.row.col.f32.f16.f16.f32 "
        "{%0,%1,%2,%3},{%4,%5,%6,%7},{%8,%9},{%0,%1,%2,%3};"
        : "+f"(c[0]), "+f"(c[1]), "+f"(c[2]), "+f"(c[3])
        : "r"(a[0]), "r"(a[1]), "r"(a[2]), "r"(a[3]), "r"(b0), "r"(b1));
}
// split two fp32 into packed fp16 hi + packed fp16 lo (p0 in low half)
__device__ __forceinline__ void split2h(float p0, float p1, uint32 &h, uint32 &l) {
    __half2 hh = __floats2half2_rn(p0, p1);
    float2 hf = __half22float2(hh);
    __half2 ll = __floats2half2_rn(p0 - hf.x, p1 - hf.y);
    h = *(uint32*)&hh;
    l = *(uint32*)&ll;
}
__device__ __forceinline__ uint32 pack2h(float p0, float p1) {
    __half2 hh = __floats2half2_rn(p0, p1);
    return *(uint32*)&hh;
}
__device__ __forceinline__ void cvt4h(float4 v, uint2 &hi, uint2 &lo) {
    split2h(v.x, v.y, hi.x, lo.x);
    split2h(v.z, v.w, hi.y, lo.y);
}
__device__ __forceinline__ uint2 cvt4h1(float4 v) {
    return make_uint2(pack2h(v.x, v.y), pack2h(v.z, v.w));
}

// Scratch
__device__ float g_q[(size_t)M_*H_*HD_];
__device__ float g_k[(size_t)M_*G_*HD_];
__device__ float g_v[(size_t)M_*G_*HD_];
__device__ float g_ctx[(size_t)M_*H_*HD_];

// ---------------------------------------------------------------------------
// NT GEMM, fp16 2-term split (A = hi+lo fp16, B = fp16), double-buffered.
// C = A@B^T, CTA tile 128x128x32, 256 threads, warp tile 32x64, fp32 io.
// ---------------------------------------------------------------------------
#define BM 128
#define BN 128
#define BKK 32
#define ASTR 40
#define STAGE_ELEMS (BM*ASTR*2 + BM*ASTR)     // Ah+Al+Bh = 15360 halves
#define SMEM_BYTES  (2 * STAGE_ELEMS * 2)      // 2 stages = 61440 B

__device__ __forceinline__ void gemm_body(
    const float* __restrict__ A, const float* __restrict__ Bm,
    float* __restrict__ C, int N, int K, int m0, int n0, __half* sm)
{
    const int tid  = threadIdx.x;
    const int lane = tid & 31;
    const int warp = tid >> 5;
    const int wm = (warp >> 1) * 32;   // 4 warps along M -> 128
    const int wn = (warp & 1) * 64;    // 2 warps along N -> 128

    const int a_lr = lane & 15;
    const int a_k8 = ((lane >> 4) & 1) << 3;
    const int b_nr = (((lane >> 4) & 1) << 3) | (lane & 7);
    const int b_k8 = ((lane >> 3) & 1) << 3;

    float acc[2][8][4];
    #pragma unroll
    for (int i = 0; i < 2; i++)
        #pragma unroll
        for (int j = 0; j < 8; j++)
            #pragma unroll
            for (int t = 0; t < 4; t++) acc[i][j][t] = 0.f;

    // register staging: A 128x32 fp32 = 4 float4/thread, B 128x32 = 4 float4/thread
    float4 ar[4], br[4];
    #pragma unroll
    for (int it = 0; it < 4; it++) {
        int f = it * 256 + tid, row = f >> 3, c4 = f & 7;
        ar[it] = *(const float4*)(A + (size_t)(m0 + row) * K + c4 * 4);
        br[it] = *(const float4*)(Bm + (size_t)(n0 + row) * K + c4 * 4);
    }

    for (int kb = 0; kb < K; kb += BKK) {
        const int st = (kb >> 5) & 1;
        __half* Ah = sm + st * STAGE_ELEMS;
        __half* Al = Ah + BM * ASTR;
        __half* Bh = Al + BM * ASTR;

        #pragma unroll
        for (int it = 0; it < 4; it++) {
            int f = it * 256 + tid, row = f >> 3, c4 = f & 7;
            uint2 hi, lo; cvt4h(ar[it], hi, lo);
            *(uint2*)&Ah[row * ASTR + c4 * 4] = hi;
            *(uint2*)&Al[row * ASTR + c4 * 4] = lo;
            *(uint2*)&Bh[row * ASTR + c4 * 4] = cvt4h1(br[it]);
        }
        __syncthreads();   // single barrier per k-block (double buffer)

        if (kb + BKK < K) {
            #pragma unroll
            for (int it = 0; it < 4; it++) {
                int f = it * 256 + tid, row = f >> 3, c4 = f & 7;
                ar[it] = *(const float4*)(A + (size_t)(m0 + row) * K + kb + BKK + c4 * 4);
                br[it] = *(const float4*)(Bm + (size_t)(n0 + row) * K + kb + BKK + c4 * 4);
            }
        }

        #pragma unroll
        for (int ks = 0; ks < BKK; ks += 16) {
            uint32 ah[2][4], al[2][4], bh[4][4];
            #pragma unroll
            for (int mi = 0; mi < 2; mi++) {
                int off = (wm + mi * 16 + a_lr) * ASTR + ks + a_k8;
                ldsm4(ah[mi][0], ah[mi][1], ah[mi][2], ah[mi][3], &Ah[off]);
                ldsm4(al[mi][0], al[mi][1], al[mi][2], al[mi][3], &Al[off]);
            }
            #pragma unroll
            for (int p = 0; p < 4; p++) {
                int off = (wn + p * 16 + b_nr) * ASTR + ks + b_k8;
                ldsm4(bh[p][0], bh[p][1], bh[p][2], bh[p][3], &Bh[off]);
            }
            #pragma unroll
            for (int mi = 0; mi < 2; mi++)
                #pragma unroll
                for (int ni = 0; ni < 8; ni++) {
                    int p = ni >> 1, s = (ni & 1) * 2;
                    mma16816h(acc[mi][ni], ah[mi], bh[p][s], bh[p][s+1]);
                    mma16816h(acc[mi][ni], al[mi], bh[p][s], bh[p][s+1]);
                }
        }
    }

    const int gq = lane >> 2, t = lane & 3;
    #pragma unroll
    for (int mi = 0; mi < 2; mi++)
        #pragma unroll
        for (int ni = 0; ni < 8; ni++) {
            int row = m0 + wm + mi * 16 + gq;
            int col = n0 + wn + ni * 8 + t * 2;
            *(float2*)(C + (size_t)row * N + col)       = make_float2(acc[mi][ni][0], acc[mi][ni][1]);
            *(float2*)(C + (size_t)(row + 8) * N + col) = make_float2(acc[mi][ni][2], acc[mi][ni][3]);
        }
}

// merged QKV projection: 24 n-blocks = 16 (Wq) + 4 (Wk) + 4 (Wv)
__global__ __launch_bounds__(256) void gemm_qkv(
    const float* __restrict__ x, const float* __restrict__ Wq,
    const float* __restrict__ Wk, const float* __restrict__ Wv)
{
    extern __shared__ __half sm[];
    int nb = blockIdx.x;
    const float* Bm; float* C; int N, n0;
    if (nb < 16)      { Bm = Wq; C = g_q; N = H_*HD_; n0 = nb * 128; }
    else if (nb < 20) { Bm = Wk; C = g_k; N = G_*HD_; n0 = (nb - 16) * 128; }
    else              { Bm = Wv; C = g_v; N = G_*HD_; n0 = (nb - 20) * 128; }
    gemm_body(x, Bm, C, N, D_, blockIdx.y * BM, n0, sm);
}

__global__ __launch_bounds__(256) void gemm_o(
    const float* __restrict__ Wo, float* __restrict__ out)
{
    extern __shared__ __half sm[];
    gemm_body(g_ctx, Wo, out, D_, H_*HD_, blockIdx.y * BM, blockIdx.x * 128, sm);
}

// ---------------------------------------------------------------------------
// Fused RMSNorm + RoPE + scalar multiply. One warp per row of 64.
// ---------------------------------------------------------------------------
__global__ __launch_bounds__(256) void rms_rope(
    float* __restrict__ t, const float* __restrict__ cosp,
    const float* __restrict__ sinp, const float* __restrict__ scale,
    int NH, float mul)
{
    const int warp = (blockIdx.x * blockDim.x + threadIdx.x) >> 5;
    const int lane = threadIdx.x & 31;
    const int s = (warp / NH) % S_;
    float* p = t + (size_t)warp * HD_;

    float t1 = p[lane];
    float t2 = p[lane + 32];
    float ss = t1 * t1 + t2 * t2;
    #pragma unroll
    for (int o = 16; o > 0; o >>= 1) ss += __shfl_xor_sync(0xffffffffu, ss, o);
    float rs = rsqrtf(ss * (1.0f / HD_) + 1e-6f);

    float n1 = t1 * rs * (1.0f + scale[lane]);
    float n2 = t2 * rs * (1.0f + scale[lane + 32]);

    float c1 = cosp[s * HD_ + lane],      c2 = cosp[s * HD_ + lane + 32];
    float s1 = sinp[s * HD_ + lane],      s2 = sinp[s * HD_ + lane + 32];
    float o1 = (n1 * c1 - n2 * s1) * mul;
    float o2 = (n2 * c2 + n1 * s2) * mul;
    p[lane]      = o1;
    p[lane + 32] = o2;
}

// ---------------------------------------------------------------------------
// Tensor-core causal flash attention, fp16 2-term split, double-buffered K/V.
// Q = qh+ql (fp16, parked in buffer 1 first), K/V single fp16, tile buf = t&1.
// Block = (b, h, 64 q-rows). 4 warps x 16 rows. Key tiles of 64. ONE sync/tile.
// ---------------------------------------------------------------------------
#define TSTR 72
#define NEG_BIG (-1e30f)

__global__ __launch_bounds__(128) void attn_tc(
    const float* __restrict__ q, const float* __restrict__ k,
    const float* __restrict__ v, float* __restrict__ ctx)
{
    __shared__ __align__(16) __half Kh[2][64*TSTR];
    __shared__ __align__(16) __half Vh[2][64*TSTR];

    const int tid  = threadIdx.x;
    const int lane = tid & 31;
    const int warp = tid >> 5;
    const int qt = blockIdx.x, h = blockIdx.y, b = blockIdx.z;
    const int g  = h / GS_;
    const int q0 = qt * 64;

    const int a_lr = lane & 15;
    const int a_k8 = ((lane >> 4) & 1) << 3;
    const int b_nr = (((lane >> 4) & 1) << 3) | (lane & 7);
    const int b_k8 = ((lane >> 3) & 1) << 3;
    const int v_r  = lane & 15;

    // ---- Q tile: hi into Kh[1], lo into Vh[1]; fragments to registers ----
    #pragma unroll
    for (int it = 0; it < 8; it++) {
        int f = it * 128 + tid, row = f >> 4, c4 = f & 15;
        float4 val = *(const float4*)(q + (((size_t)(b * S_ + q0 + row)) * H_ + h) * HD_ + c4 * 4);
        uint2 hi, lo; cvt4h(val, hi, lo);
        *(uint2*)&Kh[1][row * TSTR + c4 * 4] = hi;
        *(uint2*)&Vh[1][row * TSTR + c4 * 4] = lo;
    }
    __syncthreads();

    uint32 qh[4][4], ql[4][4];
    #pragma unroll
    for (int kc = 0; kc < 4; kc++) {
        int off = (warp * 16 + a_lr) * TSTR + kc * 16 + a_k8;
        ldsm4(qh[kc][0], qh[kc][1], qh[kc][2], qh[kc][3], &Kh[1][off]);
        ldsm4(ql[kc][0], ql[kc][1], ql[kc][2], ql[kc][3], &Vh[1][off]);
    }
    // NOTE: no sync needed here — tile 0 writes buffer 0; buffer 1 is first
    // overwritten by tile 1, whose stores happen after tile 0's sync, which
    // every warp reaches only after its q-fragment ldsm (program order).

    float octx[8][4];
    #pragma unroll
    for (int i = 0; i < 8; i++)
        #pragma unroll
        for (int j = 0; j < 4; j++) octx[i][j] = 0.f;
    float m0 = NEG_BIG, m1 = NEG_BIG, l0 = 0.f, l1 = 0.f;

    const int ntiles = qt + 1;
    for (int t = 0; t < ntiles; t++) {
        const int kt0 = t * 64;
        const int bf  = t & 1;
        __half* Kb = Kh[bf];
        __half* Vb = Vh[bf];

        // ---- K/V tiles (single fp16 conversion) into buffer t&1 ----
        #pragma unroll
        for (int it = 0; it < 8; it++) {
            int f = it * 128 + tid, row = f >> 4, c4 = f & 15;
            size_t base = (((size_t)(b * S_ + kt0 + row)) * G_ + g) * HD_ + c4 * 4;
            *(uint2*)&Kb[row * TSTR + c4 * 4] = cvt4h1(*(const float4*)(k + base));
            *(uint2*)&Vb[row * TSTR + c4 * 4] = cvt4h1(*(const float4*)(v + base));
        }
        __syncthreads();   // the ONLY barrier per tile

        // ---- Scores: S = (Qh + Ql) K^T ----
        float sc[8][4];
        #pragma unroll
        for (int i = 0; i < 8; i++)
            #pragma unroll
            for (int j = 0; j < 4; j++) sc[i][j] = 0.f;

        #pragma unroll
        for (int kg = 0; kg < 4; kg++) {
            #pragma unroll
            for (int kc = 0; kc < 4; kc++) {
                uint32 bh0, bh1, bh2, bh3;
                int off = (kg * 16 + b_nr) * TSTR + kc * 16 + b_k8;
                ldsm4(bh0, bh1, bh2, bh3, &Kb[off]);
                mma16816h(sc[2*kg],   qh[kc], bh0, bh1);
                mma16816h(sc[2*kg],   ql[kc], bh0, bh1);
                mma16816h(sc[2*kg+1], qh[kc], bh2, bh3);
                mma16816h(sc[2*kg+1], ql[kc], bh2, bh3);
            }
        }

        const int gq = lane >> 2, tt = lane & 3;
        if (kt0 == q0) {
            int qi0 = q0 + warp * 16 + gq;
            int qi1 = qi0 + 8;
            #pragma unroll
            for (int j = 0; j < 8; j++) {
                int kj = kt0 + j * 8 + tt * 2;
                if (kj     > qi0) sc[j][0] = NEG_BIG;
                if (kj + 1 > qi0) sc[j][1] = NEG_BIG;
                if (kj     > qi1) sc[j][2] = NEG_BIG;
                if (kj + 1 > qi1) sc[j][3] = NEG_BIG;
            }
        }

        // ---- Online softmax ----
        float mx0 = NEG_BIG, mx1 = NEG_BIG;
        #pragma unroll
        for (int j = 0; j < 8; j++) {
            mx0 = fmaxf(mx0, fmaxf(sc[j][0], sc[j][1]));
            mx1 = fmaxf(mx1, fmaxf(sc[j][2], sc[j][3]));
        }
        #pragma unroll
        for (int o = 1; o <= 2; o <<= 1) {
            mx0 = fmaxf(mx0, __shfl_xor_sync(0xffffffffu, mx0, o));
            mx1 = fmaxf(mx1, __shfl_xor_sync(0xffffffffu, mx1, o));
        }
        mx0 = fmaxf(mx0, m0); mx1 = fmaxf(mx1, m1);
        float alpha0 = __expf(m0 - mx0), alpha1 = __expf(m1 - mx1);
        m0 = mx0; m1 = mx1;

        float s0 = 0.f, s1 = 0.f;
        #pragma unroll
        for (int j = 0; j < 8; j++) {
            sc[j][0] = __expf(sc[j][0] - m0); s0 += sc[j][0];
            sc[j][1] = __expf(sc[j][1] - m0); s0 += sc[j][1];
            sc[j][2] = __expf(sc[j][2] - m1); s1 += sc[j][2];
            sc[j][3] = __expf(sc[j][3] - m1); s1 += sc[j][3];
        }
        #pragma unroll
        for (int o = 1; o <= 2; o <<= 1) {
            s0 += __shfl_xor_sync(0xffffffffu, s0, o);
            s1 += __shfl_xor_sync(0xffffffffu, s1, o);
        }
        l0 = l0 * alpha0 + s0;
        l1 = l1 * alpha1 + s1;

        #pragma unroll
        for (int ni = 0; ni < 8; ni++) {
            octx[ni][0] *= alpha0; octx[ni][1] *= alpha0;
            octx[ni][2] *= alpha1; octx[ni][3] *= alpha1;
        }

        // ---- P fragments (hi+lo fp16) from score fragments ----
        uint32 aph[4][4], apl[4][4];
        #pragma unroll
        for (int kc = 0; kc < 4; kc++) {
            split2h(sc[2*kc][0],   sc[2*kc][1],   aph[kc][0], apl[kc][0]);
            split2h(sc[2*kc][2],   sc[2*kc][3],   aph[kc][1], apl[kc][1]);
            split2h(sc[2*kc+1][0], sc[2*kc+1][1], aph[kc][2], apl[kc][2]);
            split2h(sc[2*kc+1][2], sc[2*kc+1][3], aph[kc][3], apl[kc][3]);
        }

        // ---- ctx += (Ph + Pl) @ V ----
        #pragma unroll
        for (int ni = 0; ni < 8; ni++) {
            #pragma unroll
            for (int kc = 0; kc < 4; kc++) {
                uint32 vh0, vh1;
                int off = (kc * 16 + v_r) * TSTR + ni * 8;
                ldsm2t(vh0, vh1, &Vb[off]);
                mma16816h(octx[ni], aph[kc], vh0, vh1);
                mma16816h(octx[ni], apl[kc], vh0, vh1);
            }
        }
        // no trailing sync — next tile writes the other buffer
    }

    // ---- Epilogue ----
    const int gq = lane >> 2, tt = lane & 3;
    float inv0 = 1.0f / l0, inv1 = 1.0f / l1;
    #pragma unroll
    for (int ni = 0; ni < 8; ni++) {
        int row = q0 + warp * 16 + gq;
        int col = ni * 8 + tt * 2;
        *(float2*)(ctx + (((size_t)(b * S_ + row)) * H_ + h) * HD_ + col) =
            make_float2(octx[ni][0] * inv0, octx[ni][1] * inv0);
        *(float2*)(ctx + (((size_t)(b * S_ + row + 8)) * H_ + h) * HD_ + col) =
            make_float2(octx[ni][2] * inv1, octx[ni][3] * inv1);
    }
}

// ---------------------------------------------------------------------------
// Launch
// ---------------------------------------------------------------------------
extern "C" void kernel_launch(void* const* d_in, const int* in_sizes, int n_in,
                              void* d_out, int out_size)
{
    (void)in_sizes; (void)n_in; (void)out_size;
    const float* x    = (const float*)d_in[0];
    const float* cosp = (const float*)d_in[2];
    const float* sinp = (const float*)d_in[3];
    const float* Wq   = (const float*)d_in[4];
    const float* Wk   = (const float*)d_in[5];
    const float* Wv   = (const float*)d_in[6];
    const float* Wo   = (const float*)d_in[7];
    const float* qsc  = (const float*)d_in[8];
    const float* ksc  = (const float*)d_in[9];
    float* out = (float*)d_out;

    float *pq, *pk, *pv, *pc;
    cudaGetSymbolAddress((void**)&pq, g_q);
    cudaGetSymbolAddress((void**)&pk, g_k);
    cudaGetSymbolAddress((void**)&pv, g_v);
    cudaGetSymbolAddress((void**)&pc, g_ctx);

    static bool attr_done = false;
    if (!attr_done) {
        cudaFuncSetAttribute(gemm_qkv, cudaFuncAttributeMaxDynamicSharedMemorySize, SMEM_BYTES);
        cudaFuncSetAttribute(gemm_o,   cudaFuncAttributeMaxDynamicSharedMemorySize, SMEM_BYTES);
        attr_done = true;
    }

    // merged QKV projection (CTA 128x128)
    gemm_qkv<<<dim3(24, M_/BM), 256, SMEM_BYTES>>>(x, Wq, Wk, Wv);

    // rmsnorm + rope
    rms_rope<<<(M_*H_)/8, 256>>>(pq, cosp, sinp, qsc, H_, 0.125f);
    rms_rope<<<(M_*G_)/8, 256>>>(pk, cosp, sinp, ksc, G_, 1.0f);

    // attention (double-buffered K/V, one sync per tile)
    attn_tc<<<dim3(S_/64, H_, B_), 128>>>(pq, pk, pv, pc);

    // output projection
    gemm_o<<<dim3(D_/128, M_/BM), 256, SMEM_BYTES>>>(Wo, out);
}